// round 2
// baseline (speedup 1.0000x reference)
#include <cuda_runtime.h>
#include <cuda_fp16.h>
#include <stdint.h>

#define WST 72                       // padded smem stride (halfs) -> conflict-free ldmatrix
#define MAT_HALFS (64 * WST)         // 4608 halfs per 64x64 matrix
#define NMAT 11
#define W_HALFS (NMAT * MAT_HALFS)
#define SMEM_BYTES (W_HALFS * 2 + 832 * 4)

// float-region offsets (in floats)
#define F_M1W 0
#define F_M1B 192
#define F_SW  256
#define F_SB  384
#define F_M2B 448
#define F_M3B 512
#define F_A0B 576
#define F_A1B 640
#define F_A2B 704
#define F_EW  768

// matrix slots in smem
#define M_M2 0
#define M_M3 1
#define M_A0 2
#define M_A1 3
#define M_A2 4
#define M_C0 5
#define M_R0 8

struct Params {
    const float *x, *t, *beta, *nu, *rho;
    const float *start_w, *start_b, *end_w, *end_b;
    const float *m1_w, *m1_b, *m2_w, *m2_b, *m3_w, *m3_b;
    const float *a0_w, *a0_b, *a1_w, *a1_b, *a2_w, *a2_b;
    const float *col0, *col1, *col2, *row0, *row1, *row2;
    float* out;
    int ntiles;
};

__device__ __forceinline__ uint32_t pack2(float lo, float hi) {
    __half2 h = __floats2half2_rn(lo, hi);
    return *reinterpret_cast<uint32_t*>(&h);
}
__device__ __forceinline__ float2 unpack2(uint32_t v) {
    __half2 h = *reinterpret_cast<__half2*>(&v);
    return __half22float2(h);
}

__device__ __forceinline__ void mma16816(float* c, const uint32_t* a, uint32_t b0, uint32_t b1) {
    asm volatile(
        "mma.sync.aligned.m16n8k16.row.col.f32.f16.f16.f32 "
        "{%0,%1,%2,%3}, {%4,%5,%6,%7}, {%8,%9}, {%0,%1,%2,%3};\n"
        : "+f"(c[0]), "+f"(c[1]), "+f"(c[2]), "+f"(c[3])
        : "r"(a[0]), "r"(a[1]), "r"(a[2]), "r"(a[3]), "r"(b0), "r"(b1));
}

__device__ __forceinline__ void ldsm4t(uint32_t& r0, uint32_t& r1, uint32_t& r2, uint32_t& r3,
                                       uint32_t addr) {
    asm volatile("ldmatrix.sync.aligned.m8n8.x4.trans.shared.b16 {%0,%1,%2,%3}, [%4];\n"
                 : "=r"(r0), "=r"(r1), "=r"(r2), "=r"(r3)
                 : "r"(addr));
}

// C[8][4] = A(16x64 frags) @ W(64x64 in smem, row-major [k][n] stride WST)
__device__ __forceinline__ void gemm64(float C[8][4], const uint32_t A[4][4],
                                       const __half* W, int lane) {
#pragma unroll
    for (int nt = 0; nt < 8; nt++)
#pragma unroll
        for (int q = 0; q < 4; q++) C[nt][q] = 0.f;

    uint32_t base = (uint32_t)__cvta_generic_to_shared(
        W + (lane & 15) * WST + ((lane & 16) ? 8 : 0));
#pragma unroll
    for (int nt2 = 0; nt2 < 4; nt2++) {
#pragma unroll
        for (int kb = 0; kb < 4; kb++) {
            uint32_t b0, b1, b2, b3;
            ldsm4t(b0, b1, b2, b3, base + (uint32_t)((kb * 16 * WST + nt2 * 16) * 2));
            mma16816(C[nt2 * 2], A[kb], b0, b1);
            mma16816(C[nt2 * 2 + 1], A[kb], b2, b3);
        }
    }
}

__device__ __forceinline__ void add_bias(float C[8][4], const float* bias, int tig) {
#pragma unroll
    for (int nt = 0; nt < 8; nt++) {
        float b0 = bias[nt * 8 + tig * 2], b1 = bias[nt * 8 + tig * 2 + 1];
        C[nt][0] += b0; C[nt][1] += b1; C[nt][2] += b0; C[nt][3] += b1;
    }
}

// C (m16n8 frags) -> A (m16k16 frags), elementwise activation applied
__device__ __forceinline__ void repack_tanh(const float C[8][4], uint32_t A[4][4]) {
#pragma unroll
    for (int kb = 0; kb < 4; kb++) {
        A[kb][0] = pack2(tanhf(C[2 * kb][0]),     tanhf(C[2 * kb][1]));
        A[kb][1] = pack2(tanhf(C[2 * kb][2]),     tanhf(C[2 * kb][3]));
        A[kb][2] = pack2(tanhf(C[2 * kb + 1][0]), tanhf(C[2 * kb + 1][1]));
        A[kb][3] = pack2(tanhf(C[2 * kb + 1][2]), tanhf(C[2 * kb + 1][3]));
    }
}
__device__ __forceinline__ void repack_id(const float C[8][4], uint32_t A[4][4]) {
#pragma unroll
    for (int kb = 0; kb < 4; kb++) {
        A[kb][0] = pack2(C[2 * kb][0],     C[2 * kb][1]);
        A[kb][1] = pack2(C[2 * kb][2],     C[2 * kb][3]);
        A[kb][2] = pack2(C[2 * kb + 1][0], C[2 * kb + 1][1]);
        A[kb][3] = pack2(C[2 * kb + 1][2], C[2 * kb + 1][3]);
    }
}

__global__ void __launch_bounds__(256)
pinn_kernel(Params p) {
    extern __shared__ char smem_raw[];
    __half* smW = reinterpret_cast<__half*>(smem_raw);
    float* smF = reinterpret_cast<float*>(smem_raw + W_HALFS * 2);
    const int tid = threadIdx.x;

    // ---- stage weights (fp32 -> fp16, padded stride) ----
    {
        const float* gsrc[NMAT] = {p.m2_w, p.m3_w, p.a0_w, p.a1_w, p.a2_w,
                                   p.col0, p.col1, p.col2, p.row0, p.row1, p.row2};
#pragma unroll
        for (int m = 0; m < NMAT; m++) {
            const float* src = gsrc[m];
            __half* dst = smW + m * MAT_HALFS;
            for (int i = tid; i < 4096; i += 256)
                dst[(i >> 6) * WST + (i & 63)] = __float2half_rn(src[i]);
        }
        if (tid < 192) smF[F_M1W + tid] = p.m1_w[tid];
        if (tid < 128) smF[F_SW + tid] = p.start_w[tid];
        if (tid < 64) {
            smF[F_M1B + tid] = p.m1_b[tid];
            smF[F_SB + tid]  = p.start_b[tid];
            smF[F_M2B + tid] = p.m2_b[tid];
            smF[F_M3B + tid] = p.m3_b[tid];
            smF[F_A0B + tid] = p.a0_b[tid];
            smF[F_A1B + tid] = p.a1_b[tid];
            smF[F_A2B + tid] = p.a2_b[tid];
            smF[F_EW  + tid] = p.end_w[tid];
        }
    }
    __syncthreads();

    const int lane = tid & 31, warp = tid >> 5;
    const int g = lane >> 2, tig = lane & 3;
    const float eb = p.end_b[0];

    for (int tile = blockIdx.x; tile < p.ntiles; tile += gridDim.x) {
        const int rowbase = tile * 128 + warp * 16;
        const int rlo = rowbase + g, rhi = rlo + 8;

        uint32_t A[4][4];
        float C[8][4];

        // ---- hypernet input layer: tanh([beta,nu,rho] @ m1_w + m1_b) ----
        {
            float b0 = p.beta[rlo], b1 = p.beta[rhi];
            float n0 = p.nu[rlo],   n1 = p.nu[rhi];
            float r0 = p.rho[rlo],  r1 = p.rho[rhi];
#pragma unroll
            for (int kb = 0; kb < 4; kb++) {
                int j0 = kb * 16 + tig * 2;
#pragma unroll
                for (int hf = 0; hf < 2; hf++) {
                    int j = j0 + hf * 8;
                    float w0a = smF[F_M1W + j],        w0b = smF[F_M1W + j + 1];
                    float w1a = smF[F_M1W + 64 + j],   w1b = smF[F_M1W + 64 + j + 1];
                    float w2a = smF[F_M1W + 128 + j],  w2b = smF[F_M1W + 128 + j + 1];
                    float ba  = smF[F_M1B + j],        bb  = smF[F_M1B + j + 1];
                    A[kb][hf * 2 + 0] = pack2(tanhf(b0 * w0a + n0 * w1a + r0 * w2a + ba),
                                              tanhf(b0 * w0b + n0 * w1b + r0 * w2b + bb));
                    A[kb][hf * 2 + 1] = pack2(tanhf(b1 * w0a + n1 * w1a + r1 * w2a + ba),
                                              tanhf(b1 * w0b + n1 * w1b + r1 * w2b + bb));
                }
            }
        }

        // m2, m3 (tanh)
        gemm64(C, A, smW + M_M2 * MAT_HALFS, lane);
        add_bias(C, smF + F_M2B, tig);
        repack_tanh(C, A);
        gemm64(C, A, smW + M_M3 * MAT_HALFS, lane);
        add_bias(C, smF + F_M3B, tig);
        repack_tanh(C, A);

        // alpha heads (relu), kept packed in C-fragment layout
        uint32_t al[3][8][2];
#pragma unroll
        for (int h = 0; h < 3; h++) {
            gemm64(C, A, smW + (M_A0 + h) * MAT_HALFS, lane);
            add_bias(C, smF + F_A0B + 64 * h, tig);
#pragma unroll
            for (int nt = 0; nt < 8; nt++) {
                al[h][nt][0] = pack2(fmaxf(C[nt][0], 0.f), fmaxf(C[nt][1], 0.f));
                al[h][nt][1] = pack2(fmaxf(C[nt][2], 0.f), fmaxf(C[nt][3], 0.f));
            }
        }

        // ---- main net input layer: tanh([x,t] @ start_w + start_b) ----
        {
            float x0 = p.x[rlo], x1 = p.x[rhi];
            float t0 = p.t[rlo], t1 = p.t[rhi];
#pragma unroll
            for (int kb = 0; kb < 4; kb++) {
                int j0 = kb * 16 + tig * 2;
#pragma unroll
                for (int hf = 0; hf < 2; hf++) {
                    int j = j0 + hf * 8;
                    float w0a = smF[F_SW + j],      w0b = smF[F_SW + j + 1];
                    float w1a = smF[F_SW + 64 + j], w1b = smF[F_SW + 64 + j + 1];
                    float ba  = smF[F_SB + j],      bb  = smF[F_SB + j + 1];
                    A[kb][hf * 2 + 0] = pack2(tanhf(x0 * w0a + t0 * w1a + ba),
                                              tanhf(x0 * w0b + t0 * w1b + bb));
                    A[kb][hf * 2 + 1] = pack2(tanhf(x1 * w0a + t1 * w1a + ba),
                                              tanhf(x1 * w0b + t1 * w1b + bb));
                }
            }
        }

        // ---- 3x: h = tanh(((h @ col) * alpha) @ row) ----
#pragma unroll
        for (int l = 0; l < 3; l++) {
            gemm64(C, A, smW + (M_C0 + l) * MAT_HALFS, lane);
#pragma unroll
            for (int nt = 0; nt < 8; nt++) {
                float2 f0 = unpack2(al[l][nt][0]);
                float2 f1 = unpack2(al[l][nt][1]);
                C[nt][0] *= f0.x; C[nt][1] *= f0.y;
                C[nt][2] *= f1.x; C[nt][3] *= f1.y;
            }
            repack_id(C, A);
            gemm64(C, A, smW + (M_R0 + l) * MAT_HALFS, lane);
            repack_tanh(C, A);
        }

        // ---- out = h @ end_w + end_b ----
        {
            float slo = 0.f, shi = 0.f;
#pragma unroll
            for (int kb = 0; kb < 4; kb++) {
                int j0 = kb * 16 + tig * 2;
                float2 f;
                f = unpack2(A[kb][0]); slo += f.x * smF[F_EW + j0]     + f.y * smF[F_EW + j0 + 1];
                f = unpack2(A[kb][1]); shi += f.x * smF[F_EW + j0]     + f.y * smF[F_EW + j0 + 1];
                f = unpack2(A[kb][2]); slo += f.x * smF[F_EW + j0 + 8] + f.y * smF[F_EW + j0 + 9];
                f = unpack2(A[kb][3]); shi += f.x * smF[F_EW + j0 + 8] + f.y * smF[F_EW + j0 + 9];
            }
            slo += __shfl_xor_sync(0xFFFFFFFFu, slo, 1);
            slo += __shfl_xor_sync(0xFFFFFFFFu, slo, 2);
            shi += __shfl_xor_sync(0xFFFFFFFFu, shi, 1);
            shi += __shfl_xor_sync(0xFFFFFFFFu, shi, 2);
            if (tig == 0) {
                p.out[rlo] = slo + eb;
                p.out[rhi] = shi + eb;
            }
        }
    }
}

// pass-through of the 6 weight matrices into the output tuple
__global__ void copy_mats(float* dst, const float* c0, const float* c1, const float* c2,
                          const float* r0, const float* r1, const float* r2) {
    int i = blockIdx.x * blockDim.x + threadIdx.x;
    if (i < 4096) {
        dst[i]            = c0[i];
        dst[4096 + i]     = c1[i];
        dst[2 * 4096 + i] = c2[i];
        dst[3 * 4096 + i] = r0[i];
        dst[4 * 4096 + i] = r1[i];
        dst[5 * 4096 + i] = r2[i];
    }
}

extern "C" void kernel_launch(void* const* d_in, const int* in_sizes, int n_in,
                              void* d_out, int out_size) {
    (void)n_in; (void)out_size;
    Params p;
    p.x       = (const float*)d_in[0];
    p.t       = (const float*)d_in[1];
    p.beta    = (const float*)d_in[2];
    p.nu      = (const float*)d_in[3];
    p.rho     = (const float*)d_in[4];
    p.start_w = (const float*)d_in[5];
    p.start_b = (const float*)d_in[6];
    p.end_w   = (const float*)d_in[7];
    p.end_b   = (const float*)d_in[8];
    p.m1_w    = (const float*)d_in[9];
    p.m1_b    = (const float*)d_in[10];
    p.m2_w    = (const float*)d_in[11];
    p.m2_b    = (const float*)d_in[12];
    p.m3_w    = (const float*)d_in[13];
    p.m3_b    = (const float*)d_in[14];
    p.a0_w    = (const float*)d_in[15];
    p.a0_b    = (const float*)d_in[16];
    p.a1_w    = (const float*)d_in[17];
    p.a1_b    = (const float*)d_in[18];
    p.a2_w    = (const float*)d_in[19];
    p.a2_b    = (const float*)d_in[20];
    p.col0    = (const float*)d_in[21];
    p.col1    = (const float*)d_in[22];
    p.col2    = (const float*)d_in[23];
    p.row0    = (const float*)d_in[24];
    p.row1    = (const float*)d_in[25];
    p.row2    = (const float*)d_in[26];
    p.out     = (float*)d_out;

    const int B = in_sizes[0];
    p.ntiles = B / 128;

    cudaFuncSetAttribute(pinn_kernel, cudaFuncAttributeMaxDynamicSharedMemorySize, SMEM_BYTES);
    int grid = p.ntiles < 2048 ? p.ntiles : 2048;
    pinn_kernel<<<grid, 256, SMEM_BYTES>>>(p);
    copy_mats<<<8, 512>>>((float*)d_out + B, p.col0, p.col1, p.col2, p.row0, p.row1, p.row2);
}

// round 3
// speedup vs baseline: 1.6811x; 1.6811x over previous
#include <cuda_runtime.h>
#include <cuda_fp16.h>
#include <stdint.h>

#define WST 72                       // padded smem stride (halfs) -> conflict-free ldmatrix
#define MAT_HALFS (64 * WST)         // 4608 halfs per 64x64 matrix
#define NMAT 11
#define W_HALFS (NMAT * MAT_HALFS)
#define SMEM_BYTES (W_HALFS * 2 + 832 * 4)

// float-region offsets (in floats)
#define F_M1W 0
#define F_M1B 192
#define F_SW  256
#define F_SB  384
#define F_M2B 448
#define F_M3B 512
#define F_A0B 576
#define F_A1B 640
#define F_A2B 704
#define F_EW  768

// matrix slots in smem
#define M_M2 0
#define M_M3 1
#define M_A0 2
#define M_A1 3
#define M_A2 4
#define M_C0 5
#define M_R0 8

struct Params {
    const float *x, *t, *beta, *nu, *rho;
    const float *start_w, *start_b, *end_w, *end_b;
    const float *m1_w, *m1_b, *m2_w, *m2_b, *m3_w, *m3_b;
    const float *a0_w, *a0_b, *a1_w, *a1_b, *a2_w, *a2_b;
    const float *col0, *col1, *col2, *row0, *row1, *row2;
    float* out;
    int ntiles;
    int B;
};

// HW tanh (MUFU.TANH): 1 instruction vs ~20 for the libm polynomial.
__device__ __forceinline__ float tanh_fast(float x) {
    float y;
    asm("tanh.approx.f32 %0, %1;" : "=f"(y) : "f"(x));
    return y;
}

__device__ __forceinline__ uint32_t pack2(float lo, float hi) {
    __half2 h = __floats2half2_rn(lo, hi);
    return *reinterpret_cast<uint32_t*>(&h);
}
__device__ __forceinline__ float2 unpack2(uint32_t v) {
    __half2 h = *reinterpret_cast<__half2*>(&v);
    return __half22float2(h);
}

__device__ __forceinline__ void mma16816(float* c, const uint32_t* a, uint32_t b0, uint32_t b1) {
    asm volatile(
        "mma.sync.aligned.m16n8k16.row.col.f32.f16.f16.f32 "
        "{%0,%1,%2,%3}, {%4,%5,%6,%7}, {%8,%9}, {%0,%1,%2,%3};\n"
        : "+f"(c[0]), "+f"(c[1]), "+f"(c[2]), "+f"(c[3])
        : "r"(a[0]), "r"(a[1]), "r"(a[2]), "r"(a[3]), "r"(b0), "r"(b1));
}

__device__ __forceinline__ void ldsm4t(uint32_t& r0, uint32_t& r1, uint32_t& r2, uint32_t& r3,
                                       uint32_t addr) {
    asm volatile("ldmatrix.sync.aligned.m8n8.x4.trans.shared.b16 {%0,%1,%2,%3}, [%4];\n"
                 : "=r"(r0), "=r"(r1), "=r"(r2), "=r"(r3)
                 : "r"(addr));
}

// C[8][4] = A(16x64 frags) @ W(64x64 in smem, row-major [k][n] stride WST)
__device__ __forceinline__ void gemm64(float C[8][4], const uint32_t A[4][4],
                                       const __half* W, int lane) {
#pragma unroll
    for (int nt = 0; nt < 8; nt++)
#pragma unroll
        for (int q = 0; q < 4; q++) C[nt][q] = 0.f;

    uint32_t base = (uint32_t)__cvta_generic_to_shared(
        W + (lane & 15) * WST + ((lane & 16) ? 8 : 0));
#pragma unroll
    for (int nt2 = 0; nt2 < 4; nt2++) {
#pragma unroll
        for (int kb = 0; kb < 4; kb++) {
            uint32_t b0, b1, b2, b3;
            ldsm4t(b0, b1, b2, b3, base + (uint32_t)((kb * 16 * WST + nt2 * 16) * 2));
            mma16816(C[nt2 * 2], A[kb], b0, b1);
            mma16816(C[nt2 * 2 + 1], A[kb], b2, b3);
        }
    }
}

__device__ __forceinline__ void add_bias(float C[8][4], const float* bias, int tig) {
#pragma unroll
    for (int nt = 0; nt < 8; nt++) {
        float b0 = bias[nt * 8 + tig * 2], b1 = bias[nt * 8 + tig * 2 + 1];
        C[nt][0] += b0; C[nt][1] += b1; C[nt][2] += b0; C[nt][3] += b1;
    }
}

// C (m16n8 frags) -> A (m16k16 frags), elementwise activation applied
__device__ __forceinline__ void repack_tanh(const float C[8][4], uint32_t A[4][4]) {
#pragma unroll
    for (int kb = 0; kb < 4; kb++) {
        A[kb][0] = pack2(tanh_fast(C[2 * kb][0]),     tanh_fast(C[2 * kb][1]));
        A[kb][1] = pack2(tanh_fast(C[2 * kb][2]),     tanh_fast(C[2 * kb][3]));
        A[kb][2] = pack2(tanh_fast(C[2 * kb + 1][0]), tanh_fast(C[2 * kb + 1][1]));
        A[kb][3] = pack2(tanh_fast(C[2 * kb + 1][2]), tanh_fast(C[2 * kb + 1][3]));
    }
}
__device__ __forceinline__ void repack_id(const float C[8][4], uint32_t A[4][4]) {
#pragma unroll
    for (int kb = 0; kb < 4; kb++) {
        A[kb][0] = pack2(C[2 * kb][0],     C[2 * kb][1]);
        A[kb][1] = pack2(C[2 * kb][2],     C[2 * kb][3]);
        A[kb][2] = pack2(C[2 * kb + 1][0], C[2 * kb + 1][1]);
        A[kb][3] = pack2(C[2 * kb + 1][2], C[2 * kb + 1][3]);
    }
}

__global__ void __launch_bounds__(256)
pinn_kernel(Params p) {
    extern __shared__ char smem_raw[];
    __half* smW = reinterpret_cast<__half*>(smem_raw);
    float* smF = reinterpret_cast<float*>(smem_raw + W_HALFS * 2);
    const int tid = threadIdx.x;

    // ---- fold in the pass-through copy (24576 floats = 6144 float4) ----
    if (blockIdx.x < 24) {
        int i = blockIdx.x * 256 + tid;  // 0..6143 float4
        const float4* s4;
        int j = i & 1023;                // float4 index within one 4096-float matrix
        int m = i >> 10;                 // which matrix 0..5
        const float* srcs[6] = {p.col0, p.col1, p.col2, p.row0, p.row1, p.row2};
        s4 = reinterpret_cast<const float4*>(srcs[m]) + j;
        reinterpret_cast<float4*>(p.out + p.B)[i] = *s4;
    }

    // ---- stage weights (fp32 -> fp16, padded stride) ----
    {
        const float* gsrc[NMAT] = {p.m2_w, p.m3_w, p.a0_w, p.a1_w, p.a2_w,
                                   p.col0, p.col1, p.col2, p.row0, p.row1, p.row2};
#pragma unroll
        for (int m = 0; m < NMAT; m++) {
            const float* src = gsrc[m];
            __half* dst = smW + m * MAT_HALFS;
            for (int i = tid; i < 4096; i += 256)
                dst[(i >> 6) * WST + (i & 63)] = __float2half_rn(src[i]);
        }
        if (tid < 192) smF[F_M1W + tid] = p.m1_w[tid];
        if (tid < 128) smF[F_SW + tid] = p.start_w[tid];
        if (tid < 64) {
            smF[F_M1B + tid] = p.m1_b[tid];
            smF[F_SB + tid]  = p.start_b[tid];
            smF[F_M2B + tid] = p.m2_b[tid];
            smF[F_M3B + tid] = p.m3_b[tid];
            smF[F_A0B + tid] = p.a0_b[tid];
            smF[F_A1B + tid] = p.a1_b[tid];
            smF[F_A2B + tid] = p.a2_b[tid];
            smF[F_EW  + tid] = p.end_w[tid];
        }
    }
    __syncthreads();

    const int lane = tid & 31, warp = tid >> 5;
    const int g = lane >> 2, tig = lane & 3;
    const float eb = p.end_b[0];

    for (int tile = blockIdx.x; tile < p.ntiles; tile += gridDim.x) {
        const int rowbase = tile * 128 + warp * 16;
        const int rlo = rowbase + g, rhi = rlo + 8;

        uint32_t A[4][4];
        float C[8][4];

        // ---- hypernet input layer: tanh([beta,nu,rho] @ m1_w + m1_b) ----
        {
            float b0 = p.beta[rlo], b1 = p.beta[rhi];
            float n0 = p.nu[rlo],   n1 = p.nu[rhi];
            float r0 = p.rho[rlo],  r1 = p.rho[rhi];
#pragma unroll
            for (int kb = 0; kb < 4; kb++) {
                int j0 = kb * 16 + tig * 2;
#pragma unroll
                for (int hf = 0; hf < 2; hf++) {
                    int j = j0 + hf * 8;
                    float w0a = smF[F_M1W + j],        w0b = smF[F_M1W + j + 1];
                    float w1a = smF[F_M1W + 64 + j],   w1b = smF[F_M1W + 64 + j + 1];
                    float w2a = smF[F_M1W + 128 + j],  w2b = smF[F_M1W + 128 + j + 1];
                    float ba  = smF[F_M1B + j],        bb  = smF[F_M1B + j + 1];
                    A[kb][hf * 2 + 0] = pack2(tanh_fast(b0 * w0a + n0 * w1a + r0 * w2a + ba),
                                              tanh_fast(b0 * w0b + n0 * w1b + r0 * w2b + bb));
                    A[kb][hf * 2 + 1] = pack2(tanh_fast(b1 * w0a + n1 * w1a + r1 * w2a + ba),
                                              tanh_fast(b1 * w0b + n1 * w1b + r1 * w2b + bb));
                }
            }
        }

        // m2, m3 (tanh)
        gemm64(C, A, smW + M_M2 * MAT_HALFS, lane);
        add_bias(C, smF + F_M2B, tig);
        repack_tanh(C, A);
        gemm64(C, A, smW + M_M3 * MAT_HALFS, lane);
        add_bias(C, smF + F_M3B, tig);
        repack_tanh(C, A);

        // alpha heads (relu), kept packed in C-fragment layout
        uint32_t al[3][8][2];
#pragma unroll
        for (int h = 0; h < 3; h++) {
            gemm64(C, A, smW + (M_A0 + h) * MAT_HALFS, lane);
            add_bias(C, smF + F_A0B + 64 * h, tig);
#pragma unroll
            for (int nt = 0; nt < 8; nt++) {
                al[h][nt][0] = pack2(fmaxf(C[nt][0], 0.f), fmaxf(C[nt][1], 0.f));
                al[h][nt][1] = pack2(fmaxf(C[nt][2], 0.f), fmaxf(C[nt][3], 0.f));
            }
        }

        // ---- main net input layer: tanh([x,t] @ start_w + start_b) ----
        {
            float x0 = p.x[rlo], x1 = p.x[rhi];
            float t0 = p.t[rlo], t1 = p.t[rhi];
#pragma unroll
            for (int kb = 0; kb < 4; kb++) {
                int j0 = kb * 16 + tig * 2;
#pragma unroll
                for (int hf = 0; hf < 2; hf++) {
                    int j = j0 + hf * 8;
                    float w0a = smF[F_SW + j],      w0b = smF[F_SW + j + 1];
                    float w1a = smF[F_SW + 64 + j], w1b = smF[F_SW + 64 + j + 1];
                    float ba  = smF[F_SB + j],      bb  = smF[F_SB + j + 1];
                    A[kb][hf * 2 + 0] = pack2(tanh_fast(x0 * w0a + t0 * w1a + ba),
                                              tanh_fast(x0 * w0b + t0 * w1b + bb));
                    A[kb][hf * 2 + 1] = pack2(tanh_fast(x1 * w0a + t1 * w1a + ba),
                                              tanh_fast(x1 * w0b + t1 * w1b + bb));
                }
            }
        }

        // ---- 3x: h = tanh(((h @ col) * alpha) @ row) ----
#pragma unroll
        for (int l = 0; l < 3; l++) {
            gemm64(C, A, smW + (M_C0 + l) * MAT_HALFS, lane);
#pragma unroll
            for (int nt = 0; nt < 8; nt++) {
                float2 f0 = unpack2(al[l][nt][0]);
                float2 f1 = unpack2(al[l][nt][1]);
                C[nt][0] *= f0.x; C[nt][1] *= f0.y;
                C[nt][2] *= f1.x; C[nt][3] *= f1.y;
            }
            repack_id(C, A);
            gemm64(C, A, smW + (M_R0 + l) * MAT_HALFS, lane);
            repack_tanh(C, A);
        }

        // ---- out = h @ end_w + end_b ----
        {
            float slo = 0.f, shi = 0.f;
#pragma unroll
            for (int kb = 0; kb < 4; kb++) {
                int j0 = kb * 16 + tig * 2;
                float2 f;
                f = unpack2(A[kb][0]); slo += f.x * smF[F_EW + j0]     + f.y * smF[F_EW + j0 + 1];
                f = unpack2(A[kb][1]); shi += f.x * smF[F_EW + j0]     + f.y * smF[F_EW + j0 + 1];
                f = unpack2(A[kb][2]); slo += f.x * smF[F_EW + j0 + 8] + f.y * smF[F_EW + j0 + 9];
                f = unpack2(A[kb][3]); shi += f.x * smF[F_EW + j0 + 8] + f.y * smF[F_EW + j0 + 9];
            }
            slo += __shfl_xor_sync(0xFFFFFFFFu, slo, 1);
            slo += __shfl_xor_sync(0xFFFFFFFFu, slo, 2);
            shi += __shfl_xor_sync(0xFFFFFFFFu, shi, 1);
            shi += __shfl_xor_sync(0xFFFFFFFFu, shi, 2);
            if (tig == 0) {
                p.out[rlo] = slo + eb;
                p.out[rhi] = shi + eb;
            }
        }
    }
}

extern "C" void kernel_launch(void* const* d_in, const int* in_sizes, int n_in,
                              void* d_out, int out_size) {
    (void)n_in; (void)out_size;
    Params p;
    p.x       = (const float*)d_in[0];
    p.t       = (const float*)d_in[1];
    p.beta    = (const float*)d_in[2];
    p.nu      = (const float*)d_in[3];
    p.rho     = (const float*)d_in[4];
    p.start_w = (const float*)d_in[5];
    p.start_b = (const float*)d_in[6];
    p.end_w   = (const float*)d_in[7];
    p.end_b   = (const float*)d_in[8];
    p.m1_w    = (const float*)d_in[9];
    p.m1_b    = (const float*)d_in[10];
    p.m2_w    = (const float*)d_in[11];
    p.m2_b    = (const float*)d_in[12];
    p.m3_w    = (const float*)d_in[13];
    p.m3_b    = (const float*)d_in[14];
    p.a0_w    = (const float*)d_in[15];
    p.a0_b    = (const float*)d_in[16];
    p.a1_w    = (const float*)d_in[17];
    p.a1_b    = (const float*)d_in[18];
    p.a2_w    = (const float*)d_in[19];
    p.a2_b    = (const float*)d_in[20];
    p.col0    = (const float*)d_in[21];
    p.col1    = (const float*)d_in[22];
    p.col2    = (const float*)d_in[23];
    p.row0    = (const float*)d_in[24];
    p.row1    = (const float*)d_in[25];
    p.row2    = (const float*)d_in[26];
    p.out     = (float*)d_out;

    p.B = in_sizes[0];
    p.ntiles = p.B / 128;

    cudaFuncSetAttribute(pinn_kernel, cudaFuncAttributeMaxDynamicSharedMemorySize, SMEM_BYTES);
    int grid = p.ntiles < 2048 ? p.ntiles : 2048;
    pinn_kernel<<<grid, 256, SMEM_BYTES>>>(p);
}

// round 4
// speedup vs baseline: 2.1705x; 1.2911x over previous
#include <cuda_runtime.h>
#include <cuda_fp16.h>
#include <stdint.h>

#define WST 72                       // padded smem stride (halfs) -> conflict-free ldmatrix
#define MAT_HALFS (64 * WST)         // 4608 halfs per 64x64 matrix
#define NMAT 11
#define W_HALFS (NMAT * MAT_HALFS)
#define SMEM_BYTES (W_HALFS * 2 + 832 * 4)

// float-region offsets (in floats)
#define F_M1W 0
#define F_M1B 192
#define F_SW  256
#define F_SB  384
#define F_M2B 448
#define F_M3B 512
#define F_A0B 576
#define F_A1B 640
#define F_A2B 704
#define F_EW  768

// matrix slots in smem
#define M_M2 0
#define M_M3 1
#define M_A0 2
#define M_A1 3
#define M_A2 4
#define M_C0 5
#define M_R0 8

struct Params {
    const float *x, *t, *beta, *nu, *rho;
    const float *start_w, *start_b, *end_w, *end_b;
    const float *m1_w, *m1_b, *m2_w, *m2_b, *m3_w, *m3_b;
    const float *a0_w, *a0_b, *a1_w, *a1_b, *a2_w, *a2_b;
    const float *col0, *col1, *col2, *row0, *row1, *row2;
    float* out;
    int ntiles;
    int B;
};

// HW tanh (MUFU.TANH)
__device__ __forceinline__ float tanh_fast(float x) {
    float y;
    asm("tanh.approx.f32 %0, %1;" : "=f"(y) : "f"(x));
    return y;
}

__device__ __forceinline__ uint32_t pack2(float lo, float hi) {
    __half2 h = __floats2half2_rn(lo, hi);
    return *reinterpret_cast<uint32_t*>(&h);
}
__device__ __forceinline__ float2 unpack2(uint32_t v) {
    __half2 h = *reinterpret_cast<__half2*>(&v);
    return __half22float2(h);
}

__device__ __forceinline__ void mma16816(float* c, const uint32_t* a, uint32_t b0, uint32_t b1) {
    asm volatile(
        "mma.sync.aligned.m16n8k16.row.col.f32.f16.f16.f32 "
        "{%0,%1,%2,%3}, {%4,%5,%6,%7}, {%8,%9}, {%0,%1,%2,%3};\n"
        : "+f"(c[0]), "+f"(c[1]), "+f"(c[2]), "+f"(c[3])
        : "r"(a[0]), "r"(a[1]), "r"(a[2]), "r"(a[3]), "r"(b0), "r"(b1));
}

__device__ __forceinline__ void ldsm4t(uint32_t& r0, uint32_t& r1, uint32_t& r2, uint32_t& r3,
                                       uint32_t addr) {
    asm volatile("ldmatrix.sync.aligned.m8n8.x4.trans.shared.b16 {%0,%1,%2,%3}, [%4];\n"
                 : "=r"(r0), "=r"(r1), "=r"(r2), "=r"(r3)
                 : "r"(addr));
}

// C[8][4] = A(16x64 frags) @ W(64x64 in smem, row-major [k][n] stride WST)
__device__ __forceinline__ void gemm64(float C[8][4], const uint32_t A[4][4],
                                       const __half* W, int lane) {
#pragma unroll
    for (int nt = 0; nt < 8; nt++)
#pragma unroll
        for (int q = 0; q < 4; q++) C[nt][q] = 0.f;

    uint32_t base = (uint32_t)__cvta_generic_to_shared(
        W + (lane & 15) * WST + ((lane & 16) ? 8 : 0));
#pragma unroll
    for (int nt2 = 0; nt2 < 4; nt2++) {
#pragma unroll
        for (int kb = 0; kb < 4; kb++) {
            uint32_t b0, b1, b2, b3;
            ldsm4t(b0, b1, b2, b3, base + (uint32_t)((kb * 16 * WST + nt2 * 16) * 2));
            mma16816(C[nt2 * 2], A[kb], b0, b1);
            mma16816(C[nt2 * 2 + 1], A[kb], b2, b3);
        }
    }
}

__device__ __forceinline__ void add_bias(float C[8][4], const float* bias, int tig) {
#pragma unroll
    for (int nt = 0; nt < 8; nt++) {
        float b0 = bias[nt * 8 + tig * 2], b1 = bias[nt * 8 + tig * 2 + 1];
        C[nt][0] += b0; C[nt][1] += b1; C[nt][2] += b0; C[nt][3] += b1;
    }
}

// C (m16n8 frags) -> A (m16k16 frags), elementwise activation applied
__device__ __forceinline__ void repack_tanh(const float C[8][4], uint32_t A[4][4]) {
#pragma unroll
    for (int kb = 0; kb < 4; kb++) {
        A[kb][0] = pack2(tanh_fast(C[2 * kb][0]),     tanh_fast(C[2 * kb][1]));
        A[kb][1] = pack2(tanh_fast(C[2 * kb][2]),     tanh_fast(C[2 * kb][3]));
        A[kb][2] = pack2(tanh_fast(C[2 * kb + 1][0]), tanh_fast(C[2 * kb + 1][1]));
        A[kb][3] = pack2(tanh_fast(C[2 * kb + 1][2]), tanh_fast(C[2 * kb + 1][3]));
    }
}
__device__ __forceinline__ void repack_id(const float C[8][4], uint32_t A[4][4]) {
#pragma unroll
    for (int kb = 0; kb < 4; kb++) {
        A[kb][0] = pack2(C[2 * kb][0],     C[2 * kb][1]);
        A[kb][1] = pack2(C[2 * kb][2],     C[2 * kb][3]);
        A[kb][2] = pack2(C[2 * kb + 1][0], C[2 * kb + 1][1]);
        A[kb][3] = pack2(C[2 * kb + 1][2], C[2 * kb + 1][3]);
    }
}

__global__ void __launch_bounds__(256, 2)
pinn_kernel(Params p) {
    extern __shared__ char smem_raw[];
    __half* smW = reinterpret_cast<__half*>(smem_raw);
    float* smF = reinterpret_cast<float*>(smem_raw + W_HALFS * 2);
    const int tid = threadIdx.x;

    // ---- fold in the pass-through copy (24576 floats = 6144 float4) ----
    if (blockIdx.x < 24) {
        int i = blockIdx.x * 256 + tid;  // 0..6143 float4
        int j = i & 1023;                // float4 index within one 4096-float matrix
        int m = i >> 10;                 // which matrix 0..5
        const float* srcs[6] = {p.col0, p.col1, p.col2, p.row0, p.row1, p.row2};
        const float4* s4 = reinterpret_cast<const float4*>(srcs[m]) + j;
        reinterpret_cast<float4*>(p.out + p.B)[i] = *s4;
    }

    // ---- stage weights (fp32 -> fp16, padded stride) ----
    {
        const float* gsrc[NMAT] = {p.m2_w, p.m3_w, p.a0_w, p.a1_w, p.a2_w,
                                   p.col0, p.col1, p.col2, p.row0, p.row1, p.row2};
#pragma unroll
        for (int m = 0; m < NMAT; m++) {
            const float* src = gsrc[m];
            __half* dst = smW + m * MAT_HALFS;
            for (int i = tid; i < 4096; i += 256)
                dst[(i >> 6) * WST + (i & 63)] = __float2half_rn(src[i]);
        }
        if (tid < 192) smF[F_M1W + tid] = p.m1_w[tid];
        if (tid < 128) smF[F_SW + tid] = p.start_w[tid];
        if (tid < 64) {
            smF[F_M1B + tid] = p.m1_b[tid];
            smF[F_SB + tid]  = p.start_b[tid];
            smF[F_M2B + tid] = p.m2_b[tid];
            smF[F_M3B + tid] = p.m3_b[tid];
            smF[F_A0B + tid] = p.a0_b[tid];
            smF[F_A1B + tid] = p.a1_b[tid];
            smF[F_A2B + tid] = p.a2_b[tid];
            smF[F_EW  + tid] = p.end_w[tid];
        }
    }
    __syncthreads();

    const int lane = tid & 31, warp = tid >> 5;
    const int g = lane >> 2, tig = lane & 3;
    const float eb = p.end_b[0];

    for (int tile = blockIdx.x; tile < p.ntiles; tile += gridDim.x) {
        const int rowbase = tile * 128 + warp * 16;
        const int rlo = rowbase + g, rhi = rlo + 8;

        uint32_t M[4][4];   // hypernet hidden state (A-fragments), live across layer loop
        uint32_t A[4][4];   // main-net h (A-fragments)
        float C[8][4];

        // ---- hypernet input layer: tanh([beta,nu,rho] @ m1_w + m1_b) ----
        {
            float b0 = p.beta[rlo], b1 = p.beta[rhi];
            float n0 = p.nu[rlo],   n1 = p.nu[rhi];
            float r0 = p.rho[rlo],  r1 = p.rho[rhi];
#pragma unroll
            for (int kb = 0; kb < 4; kb++) {
                int j0 = kb * 16 + tig * 2;
#pragma unroll
                for (int hf = 0; hf < 2; hf++) {
                    int j = j0 + hf * 8;
                    float w0a = smF[F_M1W + j],        w0b = smF[F_M1W + j + 1];
                    float w1a = smF[F_M1W + 64 + j],   w1b = smF[F_M1W + 64 + j + 1];
                    float w2a = smF[F_M1W + 128 + j],  w2b = smF[F_M1W + 128 + j + 1];
                    float ba  = smF[F_M1B + j],        bb  = smF[F_M1B + j + 1];
                    M[kb][hf * 2 + 0] = pack2(tanh_fast(b0 * w0a + n0 * w1a + r0 * w2a + ba),
                                              tanh_fast(b0 * w0b + n0 * w1b + r0 * w2b + bb));
                    M[kb][hf * 2 + 1] = pack2(tanh_fast(b1 * w0a + n1 * w1a + r1 * w2a + ba),
                                              tanh_fast(b1 * w0b + n1 * w1b + r1 * w2b + bb));
                }
            }
        }

        // m2, m3 (tanh) -> final hypernet state M
        gemm64(C, M, smW + M_M2 * MAT_HALFS, lane);
        add_bias(C, smF + F_M2B, tig);
        repack_tanh(C, M);
        gemm64(C, M, smW + M_M3 * MAT_HALFS, lane);
        add_bias(C, smF + F_M3B, tig);
        repack_tanh(C, M);

        // ---- main net input layer: tanh([x,t] @ start_w + start_b) ----
        {
            float x0 = p.x[rlo], x1 = p.x[rhi];
            float t0 = p.t[rlo], t1 = p.t[rhi];
#pragma unroll
            for (int kb = 0; kb < 4; kb++) {
                int j0 = kb * 16 + tig * 2;
#pragma unroll
                for (int hf = 0; hf < 2; hf++) {
                    int j = j0 + hf * 8;
                    float w0a = smF[F_SW + j],      w0b = smF[F_SW + j + 1];
                    float w1a = smF[F_SW + 64 + j], w1b = smF[F_SW + 64 + j + 1];
                    float ba  = smF[F_SB + j],      bb  = smF[F_SB + j + 1];
                    A[kb][hf * 2 + 0] = pack2(tanh_fast(x0 * w0a + t0 * w1a + ba),
                                              tanh_fast(x0 * w0b + t0 * w1b + bb));
                    A[kb][hf * 2 + 1] = pack2(tanh_fast(x1 * w0a + t1 * w1a + ba),
                                              tanh_fast(x1 * w0b + t1 * w1b + bb));
                }
            }
        }

        // ---- 3x: alpha_l = relu(M @ a_l); h = tanh(((h @ col_l) * alpha_l) @ row_l) ----
#pragma unroll
        for (int l = 0; l < 3; l++) {
            // alpha head for this layer only (16 regs live)
            uint32_t al[8][2];
            gemm64(C, M, smW + (M_A0 + l) * MAT_HALFS, lane);
            add_bias(C, smF + F_A0B + 64 * l, tig);
#pragma unroll
            for (int nt = 0; nt < 8; nt++) {
                al[nt][0] = pack2(fmaxf(C[nt][0], 0.f), fmaxf(C[nt][1], 0.f));
                al[nt][1] = pack2(fmaxf(C[nt][2], 0.f), fmaxf(C[nt][3], 0.f));
            }

            gemm64(C, A, smW + (M_C0 + l) * MAT_HALFS, lane);
#pragma unroll
            for (int nt = 0; nt < 8; nt++) {
                float2 f0 = unpack2(al[nt][0]);
                float2 f1 = unpack2(al[nt][1]);
                C[nt][0] *= f0.x; C[nt][1] *= f0.y;
                C[nt][2] *= f1.x; C[nt][3] *= f1.y;
            }
            repack_id(C, A);
            gemm64(C, A, smW + (M_R0 + l) * MAT_HALFS, lane);
            repack_tanh(C, A);
        }

        // ---- out = h @ end_w + end_b ----
        {
            float slo = 0.f, shi = 0.f;
#pragma unroll
            for (int kb = 0; kb < 4; kb++) {
                int j0 = kb * 16 + tig * 2;
                float2 f;
                f = unpack2(A[kb][0]); slo += f.x * smF[F_EW + j0]     + f.y * smF[F_EW + j0 + 1];
                f = unpack2(A[kb][1]); shi += f.x * smF[F_EW + j0]     + f.y * smF[F_EW + j0 + 1];
                f = unpack2(A[kb][2]); slo += f.x * smF[F_EW + j0 + 8] + f.y * smF[F_EW + j0 + 9];
                f = unpack2(A[kb][3]); shi += f.x * smF[F_EW + j0 + 8] + f.y * smF[F_EW + j0 + 9];
            }
            slo += __shfl_xor_sync(0xFFFFFFFFu, slo, 1);
            slo += __shfl_xor_sync(0xFFFFFFFFu, slo, 2);
            shi += __shfl_xor_sync(0xFFFFFFFFu, shi, 1);
            shi += __shfl_xor_sync(0xFFFFFFFFu, shi, 2);
            if (tig == 0) {
                p.out[rlo] = slo + eb;
                p.out[rhi] = shi + eb;
            }
        }
    }
}

extern "C" void kernel_launch(void* const* d_in, const int* in_sizes, int n_in,
                              void* d_out, int out_size) {
    (void)n_in; (void)out_size;
    Params p;
    p.x       = (const float*)d_in[0];
    p.t       = (const float*)d_in[1];
    p.beta    = (const float*)d_in[2];
    p.nu      = (const float*)d_in[3];
    p.rho     = (const float*)d_in[4];
    p.start_w = (const float*)d_in[5];
    p.start_b = (const float*)d_in[6];
    p.end_w   = (const float*)d_in[7];
    p.end_b   = (const float*)d_in[8];
    p.m1_w    = (const float*)d_in[9];
    p.m1_b    = (const float*)d_in[10];
    p.m2_w    = (const float*)d_in[11];
    p.m2_b    = (const float*)d_in[12];
    p.m3_w    = (const float*)d_in[13];
    p.m3_b    = (const float*)d_in[14];
    p.a0_w    = (const float*)d_in[15];
    p.a0_b    = (const float*)d_in[16];
    p.a1_w    = (const float*)d_in[17];
    p.a1_b    = (const float*)d_in[18];
    p.a2_w    = (const float*)d_in[19];
    p.a2_b    = (const float*)d_in[20];
    p.col0    = (const float*)d_in[21];
    p.col1    = (const float*)d_in[22];
    p.col2    = (const float*)d_in[23];
    p.row0    = (const float*)d_in[24];
    p.row1    = (const float*)d_in[25];
    p.row2    = (const float*)d_in[26];
    p.out     = (float*)d_out;

    p.B = in_sizes[0];
    p.ntiles = p.B / 128;

    cudaFuncSetAttribute(pinn_kernel, cudaFuncAttributeMaxDynamicSharedMemorySize, SMEM_BYTES);
    int grid = p.ntiles < 2048 ? p.ntiles : 2048;
    pinn_kernel<<<grid, 256, SMEM_BYTES>>>(p);
}